// round 15
// baseline (speedup 1.0000x reference)
#include <cuda_runtime.h>
#include <cuda_fp16.h>
#include <cstdint>

// RNN_49684181680264 : Elman RNN forward, B=16384, T=1024, H=32.
//   h_t = tanh(h_{t-1} @ Whh + b_hh + x_t * Wxh + b_xh);  out = h_T @ Wout + b_out
//
// R15: R14 (SMSP spread) won big; critical SMSPs now run 2 warps with MUFU
// ~73% busy and ~93cyc/pair exposed latency. Tile count caps warps at 1024,
// so add streams by N-SPLIT: each 16-row tile served by 2 warps (N=16 each,
// 4 HMMA + 8 tanh + ~38 instr per warp-step) -> 2048 warps = 3.46/SMSP.
// h exchange per step: own-half A fragments reused from registers (layout
// closure per half), partner half via smem f16x2 pairs (4 STS + 4 LDS,
// conflict-free [jj][pair][lane], parity double-buffer) + 1 __syncthreads,
// hidden by other CTAs' warps in the spread regime.
// Per-tile math identical to R12/R14 (f16 W, f32 MUFU.TANH): rel_err 3.46e-4.

#define RNN_T 1024
#define RNN_H 32
#define ROWS_PER_CTA 32     // 2 tiles per CTA, 2 warps per tile
#define TT 32

typedef uint32_t u32;

__device__ __forceinline__ u32 pack_half2(float v0, float v1) {
    u32 d;
    asm("cvt.rn.f16x2.f32 %0, %1, %2;" : "=r"(d) : "f"(v1), "f"(v0));
    return d;
}
__device__ __forceinline__ void mma16816(float d[4], const u32 a[4], u32 b0, u32 b1) {
    asm volatile(
        "mma.sync.aligned.m16n8k16.row.col.f32.f16.f16.f32 "
        "{%0,%1,%2,%3}, {%4,%5,%6,%7}, {%8,%9}, {%0,%1,%2,%3};"
        : "+f"(d[0]), "+f"(d[1]), "+f"(d[2]), "+f"(d[3])
        : "r"(a[0]), "r"(a[1]), "r"(a[2]), "r"(a[3]), "r"(b0), "r"(b1));
}
__device__ __forceinline__ float tanh_mufu(float v) {
    float t;
    asm("tanh.approx.f32 %0, %1;" : "=f"(t) : "f"(v));
    return t;
}

__global__ __launch_bounds__(128)
void rnn_mma_kernel(const float* __restrict__ x,
                    const float* __restrict__ Wxh,
                    const float* __restrict__ b_xh,
                    const float* __restrict__ Whh,
                    const float* __restrict__ b_hh,
                    const float* __restrict__ Wout,
                    const float* __restrict__ b_out,
                    float* __restrict__ out)
{
    __shared__ float sX[ROWS_PER_CTA][TT + 1];
    // h exchange: [parity][tile][jj][pair][lane] (f16x2 of rows qr / qr+8)
    __shared__ u32 hbuf[2][2][4][2][32];
    __shared__ float spart[2][2][16];   // [half][tile][row]

    const int tid  = threadIdx.x;
    const int lane = tid & 31;
    const int wid  = tid >> 5;          // wid%4 -> all SMSPs used
    const int u    = wid >> 1;          // tile within CTA (0/1)
    const int half = wid & 1;           // n-half this warp owns
    const int rowb = u * 16;
    const int b0   = blockIdx.x * ROWS_PER_CTA;
    const int qr   = lane >> 2;
    const int qc   = (lane & 3) * 2;

    // ---- B fragments for MY n-half: global jj = 2*half + j, j in {0,1} ----
    u32 Bh[2][2][2];
    #pragma unroll
    for (int j = 0; j < 2; j++)
        #pragma unroll
        for (int kt = 0; kt < 2; kt++)
            #pragma unroll
            for (int r = 0; r < 2; r++) {
                int n = 8 * (2 * half + j) + qr;
                int k = 16 * kt + 8 * r + qc;
                Bh[j][kt][r] = pack_half2(Whh[k * RNN_H + n],
                                          Whh[(k + 1) * RNN_H + n]);
            }

    // ---- per-thread column constants (my half) ----
    float wxh[4], bs[4], wo[4];
    #pragma unroll
    for (int j = 0; j < 2; j++)
        #pragma unroll
        for (int e = 0; e < 2; e++) {
            int c = 8 * (2 * half + j) + qc + e;
            wxh[2 * j + e] = Wxh[c];
            bs[2 * j + e]  = b_xh[c] + b_hh[c];
            wo[2 * j + e]  = Wout[c];
        }

    // ---- A fragments (full K=32, h as f16), h = 0 ----
    u32 A[2][4];
    #pragma unroll
    for (int kt = 0; kt < 2; kt++)
        #pragma unroll
        for (int r = 0; r < 4; r++) A[kt][r] = 0u;

    float th[8];

    #pragma unroll 1
    for (int t = 0; t < RNN_T; t++) {
        const int tt = t & (TT - 1);
        if (tt == 0) {
            __syncthreads();
            #pragma unroll
            for (int i = tid; i < ROWS_PER_CTA * TT; i += 128) {
                int r = i >> 5, c = i & 31;
                sX[r][c] = x[(size_t)(b0 + r) * RNN_T + t + c];
            }
            __syncthreads();
        }

        float xv0 = sX[rowb + qr][tt];
        float xv1 = sX[rowb + qr + 8][tt];

        // seeds: D = bias + x*Wxh (my 2 n-tiles)
        float D[2][4];
        #pragma unroll
        for (int j = 0; j < 2; j++) {
            D[j][0] = fmaf(xv0, wxh[2 * j],     bs[2 * j]);
            D[j][1] = fmaf(xv0, wxh[2 * j + 1], bs[2 * j + 1]);
            D[j][2] = fmaf(xv1, wxh[2 * j],     bs[2 * j]);
            D[j][3] = fmaf(xv1, wxh[2 * j + 1], bs[2 * j + 1]);
        }

        // 4 HMMA: my 2 n-tiles x 2-deep kt chain (full-K A)
        #pragma unroll
        for (int j = 0; j < 2; j++) {
            mma16816(D[j], A[0], Bh[j][0][0], Bh[j][0][1]);
            mma16816(D[j], A[1], Bh[j][1][0], Bh[j][1][1]);
        }

        // h = tanh(D) (f32 MUFU), pack pairs, publish my half
        const int p = t & 1;
        u32 pk[2][2];   // [local j][pair: rows qr / qr+8]
        #pragma unroll
        for (int j = 0; j < 2; j++) {
            th[4 * j]     = tanh_mufu(D[j][0]);
            th[4 * j + 1] = tanh_mufu(D[j][1]);
            th[4 * j + 2] = tanh_mufu(D[j][2]);
            th[4 * j + 3] = tanh_mufu(D[j][3]);
            pk[j][0] = pack_half2(th[4 * j],     th[4 * j + 1]);
            pk[j][1] = pack_half2(th[4 * j + 2], th[4 * j + 3]);
            hbuf[p][u][2 * half + j][0][lane] = pk[j][0];
            hbuf[p][u][2 * half + j][1][lane] = pk[j][1];
        }
        __syncthreads();

        // rebuild full-K A fragments: own half from registers, partner from smem
        // A[kt][r] needs n-tile jj = 2kt+(r>>1), pair (r&1)
        if (t < RNN_T - 1) {
            #pragma unroll
            for (int kt = 0; kt < 2; kt++)
                #pragma unroll
                for (int r = 0; r < 4; r++) {
                    int jj = 2 * kt + (r >> 1);
                    if ((jj >> 1) == half)
                        A[kt][r] = pk[jj & 1][r & 1];
                    else
                        A[kt][r] = hbuf[p][u][jj][r & 1][lane];
                }
        }
    }

    // ---- epilogue: partial dot over my half, combine via smem ----
    float po0 = 0.0f, po1 = 0.0f;
    #pragma unroll
    for (int j = 0; j < 2; j++) {
        po0 = fmaf(th[4 * j],     wo[2 * j],     po0);
        po0 = fmaf(th[4 * j + 1], wo[2 * j + 1], po0);
        po1 = fmaf(th[4 * j + 2], wo[2 * j],     po1);
        po1 = fmaf(th[4 * j + 3], wo[2 * j + 1], po1);
    }
    po0 += __shfl_xor_sync(0xFFFFFFFFu, po0, 1);
    po0 += __shfl_xor_sync(0xFFFFFFFFu, po0, 2);
    po1 += __shfl_xor_sync(0xFFFFFFFFu, po1, 1);
    po1 += __shfl_xor_sync(0xFFFFFFFFu, po1, 2);
    if ((lane & 3) == 0) {
        spart[half][u][qr]     = po0;
        spart[half][u][qr + 8] = po1;
    }
    __syncthreads();
    if (tid < ROWS_PER_CTA) {
        int tu = tid >> 4, row = tid & 15;
        out[b0 + tid] = spart[0][tu][row] + spart[1][tu][row] + b_out[0];
    }
}

extern "C" void kernel_launch(void* const* d_in, const int* in_sizes, int n_in,
                              void* d_out, int out_size)
{
    const float* x     = (const float*)d_in[0];
    const float* Wxh   = (const float*)d_in[1];
    const float* b_xh  = (const float*)d_in[2];
    const float* Whh   = (const float*)d_in[3];
    const float* b_hh  = (const float*)d_in[4];
    const float* Wout  = (const float*)d_in[5];
    const float* b_out = (const float*)d_in[6];
    float* out = (float*)d_out;

    dim3 grid(16384 / ROWS_PER_CTA);   // 512 CTAs x 4 warps = 2048 warps
    dim3 blk(128);                     // 2 tiles/CTA, 2 warps/tile (n-split)
    rnn_mma_kernel<<<grid, blk>>>(x, Wxh, b_xh, Whh, b_hh, Wout, b_out, out);
}

// round 16
// speedup vs baseline: 1.3708x; 1.3708x over previous
#include <cuda_runtime.h>
#include <cuda_fp16.h>
#include <cstdint>

// RNN_49684181680264 : Elman RNN forward, B=16384, T=1024, H=32.
//   h_t = tanh(h_{t-1} @ Whh + b_hh + x_t * Wxh + b_xh);  out = h_T @ Wout + b_out
//
// R16 = R14 (best: 176us, rel_err 3.46e-4; 256 CTAs x 4 warps, 1 tile/warp,
// f16 W, 8 HMMA, f32 MUFU.TANH, CVT repack) + two SCHEDULING-ONLY changes:
//  1) x software pipeline: step tt prefetches step tt+1's x, so the 29-cyc
//     LDS leaves the loop-carried serial chain (hidden behind HMMA+tanh).
//  2) paired x layout: (row qr, row qr+8) adjacent as float2 -> 1 LDS.64
//     instead of 2 LDS.32 (conflict-free, 4-lane broadcast).
// Arithmetic bit-identical to R14: rel_err must stay exactly 3.462693e-4.

#define RNN_T 1024
#define RNN_H 32
#define WARPS 4
#define ROWS_PER_CTA (16 * WARPS)
#define TT 32
#define XW (ROWS_PER_CTA + 2)   // 66 floats/row: even -> float2 aligned

typedef uint32_t u32;

__device__ __forceinline__ u32 pack_half2(float v0, float v1) {
    u32 d;
    asm("cvt.rn.f16x2.f32 %0, %1, %2;" : "=r"(d) : "f"(v1), "f"(v0));
    return d;
}
__device__ __forceinline__ void mma16816(float d[4], const u32 a[4], u32 b0, u32 b1) {
    asm volatile(
        "mma.sync.aligned.m16n8k16.row.col.f32.f16.f16.f32 "
        "{%0,%1,%2,%3}, {%4,%5,%6,%7}, {%8,%9}, {%0,%1,%2,%3};"
        : "+f"(d[0]), "+f"(d[1]), "+f"(d[2]), "+f"(d[3])
        : "r"(a[0]), "r"(a[1]), "r"(a[2]), "r"(a[3]), "r"(b0), "r"(b1));
}
__device__ __forceinline__ float tanh_mufu(float v) {
    float t;
    asm("tanh.approx.f32 %0, %1;" : "=f"(t) : "f"(v));
    return t;
}

__global__ __launch_bounds__(128)
void rnn_mma_kernel(const float* __restrict__ x,
                    const float* __restrict__ Wxh,
                    const float* __restrict__ b_xh,
                    const float* __restrict__ Whh,
                    const float* __restrict__ b_hh,
                    const float* __restrict__ Wout,
                    const float* __restrict__ b_out,
                    float* __restrict__ out)
{
    // x tile, paired layout: sXp[tt][tile*16 + qr*2 + hi] where hi selects
    // row qr (hi=0) vs row qr+8 (hi=1) -> one float2 load per warp-step.
    __shared__ __align__(8) float sXp[TT][XW];

    const int tid  = threadIdx.x;
    const int lane = tid & 31;
    const int wid  = tid >> 5;          // wid%4 -> all 4 SMSPs used
    const int row0 = wid * 16;
    const int b0   = blockIdx.x * ROWS_PER_CTA;
    const int qr   = lane >> 2;
    const int qc   = (lane & 3) * 2;
    const int xcol = row0 + (qr << 1);  // float index of my (qr, qr+8) pair

    // ---- B fragments: W as round-to-nearest f16, register-resident ----
    u32 Bh[4][2][2];
    #pragma unroll
    for (int j = 0; j < 4; j++)
        #pragma unroll
        for (int kt = 0; kt < 2; kt++)
            #pragma unroll
            for (int r = 0; r < 2; r++) {
                int n = 8 * j + qr;
                int k = 16 * kt + 8 * r + qc;
                Bh[j][kt][r] = pack_half2(Whh[k * RNN_H + n],
                                          Whh[(k + 1) * RNN_H + n]);
            }

    // ---- per-thread column constants ----
    float wxh[8], bs[8], wo[8];
    #pragma unroll
    for (int j = 0; j < 4; j++)
        #pragma unroll
        for (int e = 0; e < 2; e++) {
            int c = 8 * j + qc + e;
            wxh[2 * j + e] = Wxh[c];
            bs[2 * j + e]  = b_xh[c] + b_hh[c];
            wo[2 * j + e]  = Wout[c];
        }

    // ---- A fragments (h as f16), h = 0 ----
    u32 Ahi[2][4];
    #pragma unroll
    for (int kt = 0; kt < 2; kt++)
        #pragma unroll
        for (int r = 0; r < 4; r++) Ahi[kt][r] = 0u;

    float th[16];

    for (int t0 = 0; t0 < RNN_T; t0 += TT) {
        __syncthreads();
        // stage x: row r of CTA, step c -> sXp[c][tile*16 + (r&7)*2 + ((r&15)>>3)]
        #pragma unroll
        for (int i = tid; i < ROWS_PER_CTA * TT; i += 128) {
            int r = i >> 5, c = i & 31;
            int col = (r & ~15) + ((r & 7) << 1) + ((r & 15) >> 3);
            sXp[c][col] = x[(size_t)(b0 + r) * RNN_T + t0 + c];
        }
        __syncthreads();

        // prime the pipeline: load step 0's x pair
        float2 xv = *reinterpret_cast<const float2*>(&sXp[0][xcol]);

        #pragma unroll 1
        for (int tt = 0; tt < TT; tt++) {
            float xv0 = xv.x;   // row qr
            float xv1 = xv.y;   // row qr+8

            // prefetch next step's x pair (LDS leaves the serial chain)
            if (tt + 1 < TT)
                xv = *reinterpret_cast<const float2*>(&sXp[tt + 1][xcol]);

            // seeds: D = bias + x*Wxh
            float D[4][4];
            #pragma unroll
            for (int j = 0; j < 4; j++) {
                D[j][0] = fmaf(xv0, wxh[2 * j],     bs[2 * j]);
                D[j][1] = fmaf(xv0, wxh[2 * j + 1], bs[2 * j + 1]);
                D[j][2] = fmaf(xv1, wxh[2 * j],     bs[2 * j]);
                D[j][3] = fmaf(xv1, wxh[2 * j + 1], bs[2 * j + 1]);
            }

            // 8 HMMA: 4 n-tiles x 2-deep kt chain
            #pragma unroll
            for (int j = 0; j < 4; j++) {
                mma16816(D[j], Ahi[0], Bh[j][0][0], Bh[j][0][1]);
                mma16816(D[j], Ahi[1], Bh[j][1][0], Bh[j][1][1]);
            }

            // h = tanh(D), f32 MUFU; repack to A fragments (layout closure)
            #pragma unroll
            for (int j = 0; j < 4; j++) {
                th[4 * j]     = tanh_mufu(D[j][0]);
                th[4 * j + 1] = tanh_mufu(D[j][1]);
                th[4 * j + 2] = tanh_mufu(D[j][2]);
                th[4 * j + 3] = tanh_mufu(D[j][3]);
            }
            #pragma unroll
            for (int kt = 0; kt < 2; kt++)
                #pragma unroll
                for (int r = 0; r < 4; r++) {
                    int j = 2 * kt + (r >> 1);
                    int e = (r & 1) * 2;
                    Ahi[kt][r] = pack_half2(th[4 * j + e], th[4 * j + e + 1]);
                }
        }
    }

    // ---- epilogue: out[b] = h . Wout + b_out ----
    float po0 = 0.0f, po1 = 0.0f;
    #pragma unroll
    for (int j = 0; j < 4; j++) {
        po0 = fmaf(th[4 * j],     wo[2 * j],     po0);
        po0 = fmaf(th[4 * j + 1], wo[2 * j + 1], po0);
        po1 = fmaf(th[4 * j + 2], wo[2 * j],     po1);
        po1 = fmaf(th[4 * j + 3], wo[2 * j + 1], po1);
    }
    po0 += __shfl_xor_sync(0xFFFFFFFFu, po0, 1);
    po0 += __shfl_xor_sync(0xFFFFFFFFu, po0, 2);
    po1 += __shfl_xor_sync(0xFFFFFFFFu, po1, 1);
    po1 += __shfl_xor_sync(0xFFFFFFFFu, po1, 2);
    if ((lane & 3) == 0) {
        float bo = b_out[0];
        out[b0 + row0 + qr]     = po0 + bo;
        out[b0 + row0 + qr + 8] = po1 + bo;
    }
}

extern "C" void kernel_launch(void* const* d_in, const int* in_sizes, int n_in,
                              void* d_out, int out_size)
{
    const float* x     = (const float*)d_in[0];
    const float* Wxh   = (const float*)d_in[1];
    const float* b_xh  = (const float*)d_in[2];
    const float* Whh   = (const float*)d_in[3];
    const float* b_hh  = (const float*)d_in[4];
    const float* Wout  = (const float*)d_in[5];
    const float* b_out = (const float*)d_in[6];
    float* out = (float*)d_out;

    dim3 grid(16384 / ROWS_PER_CTA);   // 256 CTAs x 4 warps = 1024 warps
    dim3 blk(128);
    rnn_mma_kernel<<<grid, blk>>>(x, Wxh, b_xh, Whh, b_hh, Wout, b_out, out);
}

// round 17
// speedup vs baseline: 1.4085x; 1.0275x over previous
#include <cuda_runtime.h>
#include <cuda_fp16.h>
#include <cstdint>

// RNN_49684181680264 : Elman RNN forward, B=16384, T=1024, H=32.
//   h_t = tanh(h_{t-1} @ Whh + b_hh + x_t * Wxh + b_xh);  out = h_T @ Wout + b_out
//
// R17 = R14 (best: 176us, rel_err 3.462693e-4; 256 CTAs x 4 warps, 1 tile/warp,
// f16 W, 8 HMMA, f32 MUFU.TANH, CVT repack) + cross-iteration overlap:
//  - tanh/repack split into two phases: tanh j=0,1 -> pack Ahi[kt=0];
//    tanh j=2,3 -> pack Ahi[kt=1]. Next step's kt=0 HMMAs depend only on
//    Ahi[0], so with the time loop UNROLLED x2 ptxas can issue them under
//    this step's second tanh phase.
// Arithmetic bit-identical to R14 (same ops, same per-value order):
// rel_err must stay exactly 3.462693e-4.

#define RNN_T 1024
#define RNN_H 32
#define WARPS 4
#define ROWS_PER_CTA (16 * WARPS)
#define TT 32

typedef uint32_t u32;

__device__ __forceinline__ u32 pack_half2(float v0, float v1) {
    u32 d;
    asm("cvt.rn.f16x2.f32 %0, %1, %2;" : "=r"(d) : "f"(v1), "f"(v0));
    return d;
}
__device__ __forceinline__ void mma16816(float d[4], const u32 a[4], u32 b0, u32 b1) {
    asm volatile(
        "mma.sync.aligned.m16n8k16.row.col.f32.f16.f16.f32 "
        "{%0,%1,%2,%3}, {%4,%5,%6,%7}, {%8,%9}, {%0,%1,%2,%3};"
        : "+f"(d[0]), "+f"(d[1]), "+f"(d[2]), "+f"(d[3])
        : "r"(a[0]), "r"(a[1]), "r"(a[2]), "r"(a[3]), "r"(b0), "r"(b1));
}
__device__ __forceinline__ float tanh_mufu(float v) {
    float t;
    asm("tanh.approx.f32 %0, %1;" : "=f"(t) : "f"(v));
    return t;
}

__global__ __launch_bounds__(128)
void rnn_mma_kernel(const float* __restrict__ x,
                    const float* __restrict__ Wxh,
                    const float* __restrict__ b_xh,
                    const float* __restrict__ Whh,
                    const float* __restrict__ b_hh,
                    const float* __restrict__ Wout,
                    const float* __restrict__ b_out,
                    float* __restrict__ out)
{
    __shared__ float sX[ROWS_PER_CTA][TT + 1];

    const int tid  = threadIdx.x;
    const int lane = tid & 31;
    const int wid  = tid >> 5;          // wid%4 -> all 4 SMSPs used
    const int row0 = wid * 16;
    const int b0   = blockIdx.x * ROWS_PER_CTA;
    const int qr   = lane >> 2;
    const int qc   = (lane & 3) * 2;

    // ---- B fragments: W as round-to-nearest f16, register-resident ----
    u32 Bh[4][2][2];
    #pragma unroll
    for (int j = 0; j < 4; j++)
        #pragma unroll
        for (int kt = 0; kt < 2; kt++)
            #pragma unroll
            for (int r = 0; r < 2; r++) {
                int n = 8 * j + qr;
                int k = 16 * kt + 8 * r + qc;
                Bh[j][kt][r] = pack_half2(Whh[k * RNN_H + n],
                                          Whh[(k + 1) * RNN_H + n]);
            }

    // ---- per-thread column constants ----
    float wxh[8], bs[8], wo[8];
    #pragma unroll
    for (int j = 0; j < 4; j++)
        #pragma unroll
        for (int e = 0; e < 2; e++) {
            int c = 8 * j + qc + e;
            wxh[2 * j + e] = Wxh[c];
            bs[2 * j + e]  = b_xh[c] + b_hh[c];
            wo[2 * j + e]  = Wout[c];
        }

    // ---- A fragments (h as f16), h = 0 ----
    u32 Ahi[2][4];
    #pragma unroll
    for (int kt = 0; kt < 2; kt++)
        #pragma unroll
        for (int r = 0; r < 4; r++) Ahi[kt][r] = 0u;

    float th[16];

    for (int t0 = 0; t0 < RNN_T; t0 += TT) {
        __syncthreads();
        #pragma unroll
        for (int i = tid; i < ROWS_PER_CTA * TT; i += 128) {
            int r = i >> 5, c = i & 31;
            sX[r][c] = x[(size_t)(b0 + r) * RNN_T + t0 + c];
        }
        __syncthreads();

        // unroll x2: lets ptxas issue step tt+1's kt=0 HMMAs (need only
        // Ahi[0], ready after phase-1) under step tt's phase-2 tanh/pack.
        #pragma unroll 2
        for (int tt = 0; tt < TT; tt++) {
            float xv0 = sX[row0 + qr][tt];
            float xv1 = sX[row0 + qr + 8][tt];

            // seeds: D = bias + x*Wxh
            float D[4][4];
            #pragma unroll
            for (int j = 0; j < 4; j++) {
                D[j][0] = fmaf(xv0, wxh[2 * j],     bs[2 * j]);
                D[j][1] = fmaf(xv0, wxh[2 * j + 1], bs[2 * j + 1]);
                D[j][2] = fmaf(xv1, wxh[2 * j],     bs[2 * j]);
                D[j][3] = fmaf(xv1, wxh[2 * j + 1], bs[2 * j + 1]);
            }

            // 8 HMMA: 4 n-tiles x 2-deep kt chain
            #pragma unroll
            for (int j = 0; j < 4; j++) {
                mma16816(D[j], Ahi[0], Bh[j][0][0], Bh[j][0][1]);
                mma16816(D[j], Ahi[1], Bh[j][1][0], Bh[j][1][1]);
            }

            // phase 1: tanh j=0,1 -> Ahi[kt=0]  (unblocks next step's kt=0 MMAs)
            #pragma unroll
            for (int j = 0; j < 2; j++) {
                th[4 * j]     = tanh_mufu(D[j][0]);
                th[4 * j + 1] = tanh_mufu(D[j][1]);
                th[4 * j + 2] = tanh_mufu(D[j][2]);
                th[4 * j + 3] = tanh_mufu(D[j][3]);
            }
            #pragma unroll
            for (int r = 0; r < 4; r++) {
                int j = r >> 1;
                int e = (r & 1) * 2;
                Ahi[0][r] = pack_half2(th[4 * j + e], th[4 * j + e + 1]);
            }

            // phase 2: tanh j=2,3 -> Ahi[kt=1]
            #pragma unroll
            for (int j = 2; j < 4; j++) {
                th[4 * j]     = tanh_mufu(D[j][0]);
                th[4 * j + 1] = tanh_mufu(D[j][1]);
                th[4 * j + 2] = tanh_mufu(D[j][2]);
                th[4 * j + 3] = tanh_mufu(D[j][3]);
            }
            #pragma unroll
            for (int r = 0; r < 4; r++) {
                int j = 2 + (r >> 1);
                int e = (r & 1) * 2;
                Ahi[1][r] = pack_half2(th[4 * j + e], th[4 * j + e + 1]);
            }
        }
    }

    // ---- epilogue: out[b] = h . Wout + b_out ----
    float po0 = 0.0f, po1 = 0.0f;
    #pragma unroll
    for (int j = 0; j < 4; j++) {
        po0 = fmaf(th[4 * j],     wo[2 * j],     po0);
        po0 = fmaf(th[4 * j + 1], wo[2 * j + 1], po0);
        po1 = fmaf(th[4 * j + 2], wo[2 * j],     po1);
        po1 = fmaf(th[4 * j + 3], wo[2 * j + 1], po1);
    }
    po0 += __shfl_xor_sync(0xFFFFFFFFu, po0, 1);
    po0 += __shfl_xor_sync(0xFFFFFFFFu, po0, 2);
    po1 += __shfl_xor_sync(0xFFFFFFFFu, po1, 1);
    po1 += __shfl_xor_sync(0xFFFFFFFFu, po1, 2);
    if ((lane & 3) == 0) {
        float bo = b_out[0];
        out[b0 + row0 + qr]     = po0 + bo;
        out[b0 + row0 + qr + 8] = po1 + bo;
    }
}

extern "C" void kernel_launch(void* const* d_in, const int* in_sizes, int n_in,
                              void* d_out, int out_size)
{
    const float* x     = (const float*)d_in[0];
    const float* Wxh   = (const float*)d_in[1];
    const float* b_xh  = (const float*)d_in[2];
    const float* Whh   = (const float*)d_in[3];
    const float* b_hh  = (const float*)d_in[4];
    const float* Wout  = (const float*)d_in[5];
    const float* b_out = (const float*)d_in[6];
    float* out = (float*)d_out;

    dim3 grid(16384 / ROWS_PER_CTA);   // 256 CTAs x 4 warps = 1024 warps
    dim3 blk(128);
    rnn_mma_kernel<<<grid, blk>>>(x, Wxh, b_xh, Whh, b_hh, Wout, b_out, out);
}